// round 10
// baseline (speedup 1.0000x reference)
#include <cuda_runtime.h>
#include <math.h>

#define Bsz  4096
#define Tt   512
#define INP  25
#define Hh   50
#define Gg   200
#define KTOT 76          // padded (row 75 = zero weights)
#define KSPL 38          // kh0: k in [0,38), kh1: [38,76)
#define ROWS 28
#define NTH  704         // 22 warps
#define GRID 147

typedef unsigned long long u64;

__device__ __forceinline__ float tanhap(float v) {
    float r; asm("tanh.approx.f32 %0, %1;" : "=f"(r) : "f"(v)); return r;
}
__device__ __forceinline__ float sigf(float v) {
    return fmaf(0.5f, tanhap(0.5f * v), 0.5f);
}
__device__ __forceinline__ u64 pack2(float lo, float hi) {
    u64 d; asm("mov.b64 %0, {%1, %2};" : "=l"(d) : "f"(lo), "f"(hi)); return d;
}
__device__ __forceinline__ void unpack2(u64 d, float& lo, float& hi) {
    asm("mov.b64 {%0, %1}, %2;" : "=f"(lo), "=f"(hi) : "l"(d));
}
__device__ __forceinline__ u64 fma2(u64 a, u64 b, u64 c) {
    u64 d; asm("fma.rn.f32x2 %0, %1, %2, %3;" : "=l"(d) : "l"(a), "l"(b), "l"(c)); return d;
}
__device__ __forceinline__ u64 add2(u64 a, u64 b) {
    u64 d; asm("add.rn.f32x2 %0, %1, %2;" : "=l"(d) : "l"(a), "l"(b)); return d;
}
__device__ __forceinline__ u64 shfl_xor64(u64 v, int m) {
    float lo, hi; unpack2(v, lo, hi);
    lo = __shfl_xor_sync(0xffffffffu, lo, m);
    hi = __shfl_xor_sync(0xffffffffu, hi, m);
    return pack2(lo, hi);
}

__global__ void __launch_bounds__(NTH, 1)
bayes_lstm_kernel(const float* __restrict__ x,
                  const float* __restrict__ wi_mu, const float* __restrict__ wi_rho,
                  const float* __restrict__ wh_mu, const float* __restrict__ wh_rho,
                  const float* __restrict__ b_mu,  const float* __restrict__ b_rho,
                  const float* __restrict__ lin_w, const float* __restrict__ lin_b,
                  const float* __restrict__ eps_wi, const float* __restrict__ eps_wh,
                  const float* __restrict__ eps_b,
                  float* __restrict__ out)
{
    extern __shared__ float sm[];
    float* w_s = sm;                     // [76][Gg] gate-interleaved: w_s[k][jj*4+g] = W[k][g*50+jj]
    float* xhA = w_s + KTOT * Gg;        // [76][ROWS] buf 0 (x rows 0..24, h rows 25..74, row 75 zero)
    float* xhB = xhA + KTOT * ROWS;      // [76][ROWS] buf 1

    const int tid  = threadIdx.x;
    const long row0 = (long)blockIdx.x * ROWS;

    // ---- One-time: sample fused weights into gate-interleaved layout ----
    for (int i = tid; i < 75 * Gg; i += NTH) {
        int k = i / Gg, col = i - k * Gg;          // col = g*50 + jj
        float mu, rho, ep;
        if (k < INP) { mu = wi_mu[i]; rho = wi_rho[i]; ep = eps_wi[i]; }
        else { int i2 = i - INP * Gg; mu = wh_mu[i2]; rho = wh_rho[i2]; ep = eps_wh[i2]; }
        int g = col / Hh, jj = col - g * Hh;
        w_s[k * Gg + jj * 4 + g] = fmaf(log1pf(__expf(rho)), ep, mu);
    }
    // zero pad row 75 of weights, h rows of buf 0, row 75 of both xh buffers
    for (int i = tid; i < Gg; i += NTH) w_s[75 * Gg + i] = 0.0f;
    for (int i = tid; i < Hh * ROWS; i += NTH) xhA[INP * ROWS + i] = 0.0f;
    for (int i = tid; i < ROWS; i += NTH) {
        xhA[75 * ROWS + i] = 0.0f;
        xhB[75 * ROWS + i] = 0.0f;
    }
    // x(t=0) into buf 0
    {
        const int r = tid / INP, k = tid % INP;
        if (tid < INP * ROWS) {
            float v = 0.0f;
            if (row0 + r < Bsz) v = x[(size_t)(row0 + r) * (Tt * INP) + k];
            xhA[k * ROWS + r] = v;
        }
    }

    // ---- Task map: pair per (jj, 4-row) tile; PERMUTED so a warp spans few jj, many rg ----
    // tile = tid>>1 in [0,350): rg = tile % 7 (row-group), jj = tile / 7 (h-column).
    // Within a warp: 16 tiles -> <=3 distinct jj (w-load dedup), all 7 rg.
    const bool act  = (tid < 700);
    const int  tile = act ? (tid >> 1) : 349;
    const int  kh   = tid & 1;
    const int  rg   = tile % 7;
    const int  jj   = tile / 7;          // 0..49
    const int  rr0  = rg * 4;            // rows rr0..rr0+3
    const int  kbeg = kh ? KSPL : 0;

    // bias (kh==0 lanes only; flows through the bidirectional pair reduction)
    u64 bias2[4];
    #pragma unroll
    for (int g = 0; g < 4; g++) {
        float b = 0.0f;
        if (kh == 0) {
            int j = g * Hh + jj;
            b = fmaf(log1pf(__expf(b_rho[j])), eps_b[j], b_mu[j]);
        }
        bias2[g] = pack2(b, b);
    }

    // x prefetch map (1 elem/thread)
    const int  pr = tid / INP, pk = tid % INP;
    const bool pf_ok = (tid < INP * ROWS) && (row0 + pr < Bsz);
    const size_t pf_base = pf_ok ? ((size_t)(row0 + pr) * (Tt * INP) + pk) : 0;

    // cell state in registers: this lane owns rows rr0+2*kh, rr0+2*kh+1
    float c0 = 0.0f, c1 = 0.0f;

    const float* wp = w_s + jj * 4;
    __syncthreads();

    for (int t = 0; t < Tt; ++t) {
        const float* cur = (t & 1) ? xhB : xhA;
        float*       nxt = (t & 1) ? xhA : xhB;

        float pf = 0.0f;
        if (pf_ok && t + 1 < Tt) pf = x[pf_base + (size_t)(t + 1) * INP];

        // ---- Gate GEMM: a[g][vp], vp=0 -> rows (rr0,rr0+1), vp=1 -> (rr0+2,rr0+3) ----
        u64 a0[2], a1[2], a2[2], a3[2];
        a0[0] = bias2[0]; a0[1] = bias2[0];
        a1[0] = bias2[1]; a1[1] = bias2[1];
        a2[0] = bias2[2]; a2[1] = bias2[2];
        a3[0] = bias2[3]; a3[1] = bias2[3];

        const float* wk = wp + kbeg * Gg;
        const float* vk = cur + rr0 + kbeg * ROWS;
        #pragma unroll 2
        for (int i = 0; i < KSPL; ++i) {
            float4 w4 = *(const float4*)(wk);      // (i,f,g,o) of column jj
            float4 hv = *(const float4*)(vk);      // rows rr0..rr0+3
            wk += Gg; vk += ROWS;
            u64 h01 = pack2(hv.x, hv.y);
            u64 h23 = pack2(hv.z, hv.w);
            u64 wd;
            wd = pack2(w4.x, w4.x); a0[0] = fma2(wd, h01, a0[0]); a0[1] = fma2(wd, h23, a0[1]);
            wd = pack2(w4.y, w4.y); a1[0] = fma2(wd, h01, a1[0]); a1[1] = fma2(wd, h23, a1[1]);
            wd = pack2(w4.z, w4.z); a2[0] = fma2(wd, h01, a2[0]); a2[1] = fma2(wd, h23, a2[1]);
            wd = pack2(w4.w, w4.w); a3[0] = fma2(wd, h01, a3[0]); a3[1] = fma2(wd, h23, a3[1]);
        }

        // ---- Bidirectional pair reduction: both lanes get full sums ----
        #pragma unroll
        for (int vp = 0; vp < 2; vp++) {
            a0[vp] = add2(a0[vp], shfl_xor64(a0[vp], 1));
            a1[vp] = add2(a1[vp], shfl_xor64(a1[vp], 1));
            a2[vp] = add2(a2[vp], shfl_xor64(a2[vp], 1));
            a3[vp] = add2(a3[vp], shfl_xor64(a3[vp], 1));
        }

        // ---- In-register epilogue: this lane's 2 rows (vp = kh) ----
        {
            float gi0, gi1, gf0, gf1, gg0, gg1, go0, go1;
            unpack2(a0[kh], gi0, gi1);
            unpack2(a1[kh], gf0, gf1);
            unpack2(a2[kh], gg0, gg1);
            unpack2(a3[kh], go0, go1);
            float cn0 = fmaf(sigf(gf0), c0, sigf(gi0) * tanhap(gg0));
            float cn1 = fmaf(sigf(gf1), c1, sigf(gi1) * tanhap(gg1));
            c0 = cn0; c1 = cn1;
            float h0 = sigf(go0) * tanhap(cn0);
            float h1 = sigf(go1) * tanhap(cn1);
            if (act)
                *(float2*)(nxt + (INP + jj) * ROWS + rr0 + 2 * kh) = make_float2(h0, h1);
        }

        // commit prefetched x(t+1)
        if (pf_ok && t + 1 < Tt) nxt[pk * ROWS + pr] = pf;

        __syncthreads();   // one barrier per step
    }

    // ---- Head: t=511 (odd) wrote nxt = xhA ----
    if (tid < ROWS && row0 + tid < Bsz) {
        float s = lin_b[0];
        #pragma unroll
        for (int m = 0; m < Hh; m++)
            s = fmaf(xhA[(INP + m) * ROWS + tid], lin_w[m], s);
        out[row0 + tid] = s;
    }
}

extern "C" void kernel_launch(void* const* d_in, const int* in_sizes, int n_in,
                              void* d_out, int out_size)
{
    const size_t smem_bytes =
        (size_t)(KTOT * Gg + 2 * KTOT * ROWS) * sizeof(float);   // 77824 B
    cudaFuncSetAttribute(bayes_lstm_kernel,
                         cudaFuncAttributeMaxDynamicSharedMemorySize,
                         (int)smem_bytes);
    bayes_lstm_kernel<<<GRID, NTH, smem_bytes>>>(
        (const float*)d_in[0],  (const float*)d_in[1],  (const float*)d_in[2],
        (const float*)d_in[3],  (const float*)d_in[4],  (const float*)d_in[5],
        (const float*)d_in[6],  (const float*)d_in[7],  (const float*)d_in[8],
        (const float*)d_in[9],  (const float*)d_in[10], (const float*)d_in[11],
        (float*)d_out);
}

// round 11
// speedup vs baseline: 1.1237x; 1.1237x over previous
#include <cuda_runtime.h>
#include <math.h>

#define Bsz  4096
#define Tt   512
#define INP  25
#define Hh   50
#define Gg   200
#define KTOT 76          // padded (row 75 = zero weights)
#define KQ   19          // K per ks quarter
#define ROWS 32
#define NTH  800         // 25 full warps; 50 jj x 4 rb x 4 ks
#define GRID 128         // 128 * 32 = 4096 exactly
#define XS   44          // xh row stride (floats): 16B-aligned rows, bank-tiled

typedef unsigned long long u64;

__device__ __forceinline__ float tanhap(float v) {
    float r; asm("tanh.approx.f32 %0, %1;" : "=f"(r) : "f"(v)); return r;
}
__device__ __forceinline__ float sigf(float v) {
    return fmaf(0.5f, tanhap(0.5f * v), 0.5f);
}
__device__ __forceinline__ u64 pack2(float lo, float hi) {
    u64 d; asm("mov.b64 %0, {%1, %2};" : "=l"(d) : "f"(lo), "f"(hi)); return d;
}
__device__ __forceinline__ void unpack2(u64 d, float& lo, float& hi) {
    asm("mov.b64 {%0, %1}, %2;" : "=f"(lo), "=f"(hi) : "l"(d));
}
__device__ __forceinline__ u64 fma2(u64 a, u64 b, u64 c) {
    u64 d; asm("fma.rn.f32x2 %0, %1, %2, %3;" : "=l"(d) : "l"(a), "l"(b), "l"(c)); return d;
}
__device__ __forceinline__ u64 add2(u64 a, u64 b) {
    u64 d; asm("add.rn.f32x2 %0, %1, %2;" : "=l"(d) : "l"(a), "l"(b)); return d;
}
__device__ __forceinline__ u64 shfl_xor64(u64 v, int m) {
    float lo, hi; unpack2(v, lo, hi);
    lo = __shfl_xor_sync(0xffffffffu, lo, m);
    hi = __shfl_xor_sync(0xffffffffu, hi, m);
    return pack2(lo, hi);
}

__global__ void __launch_bounds__(NTH, 1)
bayes_lstm_kernel(const float* __restrict__ x,
                  const float* __restrict__ wi_mu, const float* __restrict__ wi_rho,
                  const float* __restrict__ wh_mu, const float* __restrict__ wh_rho,
                  const float* __restrict__ b_mu,  const float* __restrict__ b_rho,
                  const float* __restrict__ lin_w, const float* __restrict__ lin_b,
                  const float* __restrict__ eps_wi, const float* __restrict__ eps_wh,
                  const float* __restrict__ eps_b,
                  float* __restrict__ out)
{
    extern __shared__ float sm[];
    float* w_s = sm;                     // [76][Gg] gate-interleaved: w_s[k][jj*4+g] = W[k][g*50+jj]
    float* xhA = w_s + KTOT * Gg;        // [76][XS] buf 0 (x rows 0..24, h rows 25..74, row 75 zero)
    float* xhB = xhA + KTOT * XS;        // [76][XS] buf 1

    const int tid  = threadIdx.x;
    const int row0 = blockIdx.x * ROWS;  // exact tiling, no bounds checks

    // ---- One-time: sample fused weights into gate-interleaved layout ----
    for (int i = tid; i < 75 * Gg; i += NTH) {
        int k = i / Gg, col = i - k * Gg;          // col = g*50 + jj
        float mu, rho, ep;
        if (k < INP) { mu = wi_mu[i]; rho = wi_rho[i]; ep = eps_wi[i]; }
        else { int i2 = i - INP * Gg; mu = wh_mu[i2]; rho = wh_rho[i2]; ep = eps_wh[i2]; }
        int g = col / Hh, jj = col - g * Hh;
        w_s[k * Gg + jj * 4 + g] = fmaf(log1pf(__expf(rho)), ep, mu);
    }
    // zero pad weight row 75, h rows of buf 0, row 75 of both xh buffers
    for (int i = tid; i < Gg; i += NTH) w_s[75 * Gg + i] = 0.0f;
    for (int i = tid; i < Hh * XS; i += NTH) xhA[INP * XS + i] = 0.0f;
    if (tid < XS) { xhA[75 * XS + tid] = 0.0f; xhB[75 * XS + tid] = 0.0f; }
    // x(t=0) into buf 0: 800 elems = 32 rows x 25 k, exactly one per thread
    const int xr = tid / INP, xk = tid - xr * INP;
    const size_t pf_base = (size_t)(row0 + xr) * (Tt * INP) + xk;
    xhA[xk * XS + xr] = x[pf_base];

    // ---- Task map: thread = (jj, rb, ks) ----
    const int ks   = tid & 3;            // K quarter
    const int unit = tid >> 2;           // 0..199
    const int rb   = unit & 3;           // row-block (8 rows)
    const int jj   = unit >> 2;          // h-column 0..49
    const int rr0  = rb * 8;
    const int kbeg = ks * KQ;
    const int p1   = ks & 1;
    const int p2   = (ks >> 1) & 1;

    // scalar biases for column jj (added post-reduction)
    const float bi = fmaf(log1pf(__expf(b_rho[jj])),          eps_b[jj],          b_mu[jj]);
    const float bf = fmaf(log1pf(__expf(b_rho[Hh + jj])),     eps_b[Hh + jj],     b_mu[Hh + jj]);
    const float bg = fmaf(log1pf(__expf(b_rho[2 * Hh + jj])), eps_b[2 * Hh + jj], b_mu[2 * Hh + jj]);
    const float bo = fmaf(log1pf(__expf(b_rho[3 * Hh + jj])), eps_b[3 * Hh + jj], b_mu[3 * Hh + jj]);

    // cell state: this lane finally owns rows rr0+2*ks, rr0+2*ks+1
    float c0 = 0.0f, c1 = 0.0f;

    const float* wp0 = w_s + jj * 4 + kbeg * Gg;
    const int    voff = rr0 + kbeg * XS;
    const int    hstore = (INP + jj) * XS + rr0 + 2 * ks;

    __syncthreads();

    for (int t = 0; t < Tt; ++t) {
        const float* cur = (t & 1) ? xhB : xhA;
        float*       nxt = (t & 1) ? xhA : xhB;

        float pf = 0.0f;
        if (t + 1 < Tt) pf = x[pf_base + (size_t)(t + 1) * INP];

        // ---- Gate GEMM over this thread's K quarter: a_g[vp], vp = rowpair in 8-row block ----
        u64 a0[4], a1[4], a2[4], a3[4];
        #pragma unroll
        for (int v = 0; v < 4; v++) { a0[v] = 0ull; a1[v] = 0ull; a2[v] = 0ull; a3[v] = 0ull; }

        const float* wk = wp0;
        const float* vk = cur + voff;
        #pragma unroll 2
        for (int i = 0; i < KQ; ++i) {
            float4 w4 = *(const float4*)(wk);          // (i,f,g,o) of column jj
            float4 hA = *(const float4*)(vk);          // rows rr0..rr0+3
            float4 hB = *(const float4*)(vk + 4);      // rows rr0+4..rr0+7
            wk += Gg; vk += XS;
            u64 h01 = pack2(hA.x, hA.y);
            u64 h23 = pack2(hA.z, hA.w);
            u64 h45 = pack2(hB.x, hB.y);
            u64 h67 = pack2(hB.z, hB.w);
            u64 wd;
            wd = pack2(w4.x, w4.x);
            a0[0] = fma2(wd, h01, a0[0]); a0[1] = fma2(wd, h23, a0[1]);
            a0[2] = fma2(wd, h45, a0[2]); a0[3] = fma2(wd, h67, a0[3]);
            wd = pack2(w4.y, w4.y);
            a1[0] = fma2(wd, h01, a1[0]); a1[1] = fma2(wd, h23, a1[1]);
            a1[2] = fma2(wd, h45, a1[2]); a1[3] = fma2(wd, h67, a1[3]);
            wd = pack2(w4.z, w4.z);
            a2[0] = fma2(wd, h01, a2[0]); a2[1] = fma2(wd, h23, a2[1]);
            a2[2] = fma2(wd, h45, a2[2]); a2[3] = fma2(wd, h67, a2[3]);
            wd = pack2(w4.w, w4.w);
            a3[0] = fma2(wd, h01, a3[0]); a3[1] = fma2(wd, h23, a3[1]);
            a3[2] = fma2(wd, h45, a3[2]); a3[3] = fma2(wd, h67, a3[3]);
        }

        // ---- 4-way split-K reduction: round 1 (xor 1), round 2 (xor 2) ----
        // Final: lane owns vp = ks -> rows rr0+2ks, rr0+2ks+1.
        u64 f0, f1, f2, f3;
        {
            u64 sA, sB, lo, hi;
            // gate i
            sA = p1 ? a0[0] : a0[1];  sB = p1 ? a0[2] : a0[3];
            sA = shfl_xor64(sA, 1);   sB = shfl_xor64(sB, 1);
            lo = add2(p1 ? a0[1] : a0[0], sA);
            hi = add2(p1 ? a0[3] : a0[2], sB);
            sA = p2 ? lo : hi;  sA = shfl_xor64(sA, 2);
            f0 = add2(p2 ? hi : lo, sA);
            // gate f
            sA = p1 ? a1[0] : a1[1];  sB = p1 ? a1[2] : a1[3];
            sA = shfl_xor64(sA, 1);   sB = shfl_xor64(sB, 1);
            lo = add2(p1 ? a1[1] : a1[0], sA);
            hi = add2(p1 ? a1[3] : a1[2], sB);
            sA = p2 ? lo : hi;  sA = shfl_xor64(sA, 2);
            f1 = add2(p2 ? hi : lo, sA);
            // gate g
            sA = p1 ? a2[0] : a2[1];  sB = p1 ? a2[2] : a2[3];
            sA = shfl_xor64(sA, 1);   sB = shfl_xor64(sB, 1);
            lo = add2(p1 ? a2[1] : a2[0], sA);
            hi = add2(p1 ? a2[3] : a2[2], sB);
            sA = p2 ? lo : hi;  sA = shfl_xor64(sA, 2);
            f2 = add2(p2 ? hi : lo, sA);
            // gate o
            sA = p1 ? a3[0] : a3[1];  sB = p1 ? a3[2] : a3[3];
            sA = shfl_xor64(sA, 1);   sB = shfl_xor64(sB, 1);
            lo = add2(p1 ? a3[1] : a3[0], sA);
            hi = add2(p1 ? a3[3] : a3[2], sB);
            sA = p2 ? lo : hi;  sA = shfl_xor64(sA, 2);
            f3 = add2(p2 ? hi : lo, sA);
        }

        // ---- In-register epilogue on this lane's 2 rows ----
        {
            float gi0, gi1, gf0, gf1, gg0, gg1, go0, go1;
            unpack2(f0, gi0, gi1);
            unpack2(f1, gf0, gf1);
            unpack2(f2, gg0, gg1);
            unpack2(f3, go0, go1);
            gi0 += bi; gi1 += bi;
            gf0 += bf; gf1 += bf;
            gg0 += bg; gg1 += bg;
            go0 += bo; go1 += bo;
            float cn0 = fmaf(sigf(gf0), c0, sigf(gi0) * tanhap(gg0));
            float cn1 = fmaf(sigf(gf1), c1, sigf(gi1) * tanhap(gg1));
            c0 = cn0; c1 = cn1;
            float h0 = sigf(go0) * tanhap(cn0);
            float h1 = sigf(go1) * tanhap(cn1);
            *(float2*)(nxt + hstore) = make_float2(h0, h1);
        }

        // commit prefetched x(t+1)
        if (t + 1 < Tt) nxt[xk * XS + xr] = pf;

        __syncthreads();   // one barrier per step
    }

    // ---- Head: t=511 (odd) wrote nxt = xhA ----
    if (tid < ROWS) {
        float s = lin_b[0];
        #pragma unroll
        for (int m = 0; m < Hh; m++)
            s = fmaf(xhA[(INP + m) * XS + tid], lin_w[m], s);
        out[row0 + tid] = s;
    }
}

extern "C" void kernel_launch(void* const* d_in, const int* in_sizes, int n_in,
                              void* d_out, int out_size)
{
    const size_t smem_bytes =
        (size_t)(KTOT * Gg + 2 * KTOT * XS) * sizeof(float);   // 87552 B
    cudaFuncSetAttribute(bayes_lstm_kernel,
                         cudaFuncAttributeMaxDynamicSharedMemorySize,
                         (int)smem_bytes);
    bayes_lstm_kernel<<<GRID, NTH, smem_bytes>>>(
        (const float*)d_in[0],  (const float*)d_in[1],  (const float*)d_in[2],
        (const float*)d_in[3],  (const float*)d_in[4],  (const float*)d_in[5],
        (const float*)d_in[6],  (const float*)d_in[7],  (const float*)d_in[8],
        (const float*)d_in[9],  (const float*)d_in[10], (const float*)d_in[11],
        (float*)d_out);
}

// round 12
// speedup vs baseline: 1.4402x; 1.2816x over previous
#include <cuda_runtime.h>
#include <math.h>

#define Bsz  4096
#define Tt   512
#define INP  25
#define Hh   50
#define Gg   200
#define KTOT 76          // padded (row 75 = zero weights)
#define KSPL 38          // kh0: k in [0,38), kh1: [38,76)
#define ROWS 32
#define NTH  800         // 25 full warps; 400 pair-tiles
#define GRID 128         // 128 * 32 = 4096 exactly
#define XS   40          // xh row stride: kh bank offset = 38*40 % 32 = 16 (complementary)

typedef unsigned long long u64;

__device__ __forceinline__ float tanhap(float v) {
    float r; asm("tanh.approx.f32 %0, %1;" : "=f"(r) : "f"(v)); return r;
}
__device__ __forceinline__ float sigf(float v) {
    return fmaf(0.5f, tanhap(0.5f * v), 0.5f);
}
__device__ __forceinline__ u64 pack2(float lo, float hi) {
    u64 d; asm("mov.b64 %0, {%1, %2};" : "=l"(d) : "f"(lo), "f"(hi)); return d;
}
__device__ __forceinline__ void unpack2(u64 d, float& lo, float& hi) {
    asm("mov.b64 {%0, %1}, %2;" : "=f"(lo), "=f"(hi) : "l"(d));
}
__device__ __forceinline__ u64 fma2(u64 a, u64 b, u64 c) {
    u64 d; asm("fma.rn.f32x2 %0, %1, %2, %3;" : "=l"(d) : "l"(a), "l"(b), "l"(c)); return d;
}
__device__ __forceinline__ u64 add2(u64 a, u64 b) {
    u64 d; asm("add.rn.f32x2 %0, %1, %2;" : "=l"(d) : "l"(a), "l"(b)); return d;
}
__device__ __forceinline__ u64 shfl_xor64(u64 v, int m) {
    float lo, hi; unpack2(v, lo, hi);
    lo = __shfl_xor_sync(0xffffffffu, lo, m);
    hi = __shfl_xor_sync(0xffffffffu, hi, m);
    return pack2(lo, hi);
}

__global__ void __launch_bounds__(NTH, 1)
bayes_lstm_kernel(const float* __restrict__ x,
                  const float* __restrict__ wi_mu, const float* __restrict__ wi_rho,
                  const float* __restrict__ wh_mu, const float* __restrict__ wh_rho,
                  const float* __restrict__ b_mu,  const float* __restrict__ b_rho,
                  const float* __restrict__ lin_w, const float* __restrict__ lin_b,
                  const float* __restrict__ eps_wi, const float* __restrict__ eps_wh,
                  const float* __restrict__ eps_b,
                  float* __restrict__ out)
{
    extern __shared__ float sm[];
    float* w_s = sm;                     // [76][Gg] gate-interleaved: w_s[k][jj*4+g] = W[k][g*50+jj]
    float* xhA = w_s + KTOT * Gg;        // [76][XS] buf 0 (x rows 0..24, h rows 25..74, row 75 zero)
    float* xhB = xhA + KTOT * XS;        // [76][XS] buf 1

    const int tid  = threadIdx.x;
    const int row0 = blockIdx.x * ROWS;  // exact tiling

    // ---- One-time: sample fused weights into gate-interleaved layout ----
    for (int i = tid; i < 75 * Gg; i += NTH) {
        int k = i / Gg, col = i - k * Gg;          // col = g*50 + jj
        float mu, rho, ep;
        if (k < INP) { mu = wi_mu[i]; rho = wi_rho[i]; ep = eps_wi[i]; }
        else { int i2 = i - INP * Gg; mu = wh_mu[i2]; rho = wh_rho[i2]; ep = eps_wh[i2]; }
        int g = col / Hh, jj = col - g * Hh;
        w_s[k * Gg + jj * 4 + g] = fmaf(log1pf(__expf(rho)), ep, mu);
    }
    // zero pad weight row 75; h rows of buf 0; row 75 of both xh buffers
    for (int i = tid; i < Gg; i += NTH) w_s[75 * Gg + i] = 0.0f;
    for (int i = tid; i < Hh * XS; i += NTH) xhA[INP * XS + i] = 0.0f;
    if (tid < XS) { xhA[75 * XS + tid] = 0.0f; xhB[75 * XS + tid] = 0.0f; }
    // x(t=0): 800 elems = 32 rows x 25 k, exactly one per thread
    const int xr = tid / INP, xk = tid - xr * INP;
    const size_t pf_base = (size_t)(row0 + xr) * (Tt * INP) + xk;
    xhA[xk * XS + xr] = x[pf_base];

    // ---- Task map: pair tile T = tid>>1; warp = 4 jj x 4 rg rectangle ----
    const int T  = tid >> 1;
    const int kh = tid & 1;
    int jj, rg;
    if (T < 384) {
        int blk = T >> 4, off = T & 15;
        jj = (blk >> 1) * 4 + (off & 3);
        rg = (blk & 1) * 4 + (off >> 2);
    } else {
        int off = T - 384;
        jj = 48 + (off & 1);
        rg = off >> 1;
    }
    const int rr0  = rg * 4;
    const int kbeg = kh ? KSPL : 0;

    // bias (kh==0 lanes only; flows through the bidirectional pair reduction)
    u64 bias2[4];
    #pragma unroll
    for (int g = 0; g < 4; g++) {
        float b = 0.0f;
        if (kh == 0) {
            int j = g * Hh + jj;
            b = fmaf(log1pf(__expf(b_rho[j])), eps_b[j], b_mu[j]);
        }
        bias2[g] = pack2(b, b);
    }

    // cell state in registers: this lane owns rows rr0+2*kh, rr0+2*kh+1
    float c0 = 0.0f, c1 = 0.0f;

    const float* wp = w_s + jj * 4;
    const int hstore = (INP + jj) * XS + rr0 + 2 * kh;
    __syncthreads();

    for (int t = 0; t < Tt; ++t) {
        const float* cur = (t & 1) ? xhB : xhA;
        float*       nxt = (t & 1) ? xhA : xhB;

        float pf = 0.0f;
        if (t + 1 < Tt) pf = x[pf_base + (size_t)(t + 1) * INP];

        // ---- Gate GEMM (identical instruction stream to R9) ----
        u64 a0[2], a1[2], a2[2], a3[2];
        a0[0] = bias2[0]; a0[1] = bias2[0];
        a1[0] = bias2[1]; a1[1] = bias2[1];
        a2[0] = bias2[2]; a2[1] = bias2[2];
        a3[0] = bias2[3]; a3[1] = bias2[3];

        const float* wk = wp + kbeg * Gg;
        const float* vk = cur + rr0 + kbeg * XS;
        #pragma unroll 2
        for (int i = 0; i < KSPL; ++i) {
            float4 w4 = *(const float4*)(wk);      // (i,f,g,o) of column jj
            float4 hv = *(const float4*)(vk);      // rows rr0..rr0+3
            wk += Gg; vk += XS;
            u64 h01 = pack2(hv.x, hv.y);
            u64 h23 = pack2(hv.z, hv.w);
            u64 wd;
            wd = pack2(w4.x, w4.x); a0[0] = fma2(wd, h01, a0[0]); a0[1] = fma2(wd, h23, a0[1]);
            wd = pack2(w4.y, w4.y); a1[0] = fma2(wd, h01, a1[0]); a1[1] = fma2(wd, h23, a1[1]);
            wd = pack2(w4.z, w4.z); a2[0] = fma2(wd, h01, a2[0]); a2[1] = fma2(wd, h23, a2[1]);
            wd = pack2(w4.w, w4.w); a3[0] = fma2(wd, h01, a3[0]); a3[1] = fma2(wd, h23, a3[1]);
        }

        // ---- Bidirectional pair reduction: both lanes get full sums ----
        #pragma unroll
        for (int vp = 0; vp < 2; vp++) {
            a0[vp] = add2(a0[vp], shfl_xor64(a0[vp], 1));
            a1[vp] = add2(a1[vp], shfl_xor64(a1[vp], 1));
            a2[vp] = add2(a2[vp], shfl_xor64(a2[vp], 1));
            a3[vp] = add2(a3[vp], shfl_xor64(a3[vp], 1));
        }

        // ---- In-register epilogue: this lane's 2 rows (vp = kh) ----
        {
            float gi0, gi1, gf0, gf1, gg0, gg1, go0, go1;
            unpack2(a0[kh], gi0, gi1);
            unpack2(a1[kh], gf0, gf1);
            unpack2(a2[kh], gg0, gg1);
            unpack2(a3[kh], go0, go1);
            float cn0 = fmaf(sigf(gf0), c0, sigf(gi0) * tanhap(gg0));
            float cn1 = fmaf(sigf(gf1), c1, sigf(gi1) * tanhap(gg1));
            c0 = cn0; c1 = cn1;
            float h0 = sigf(go0) * tanhap(cn0);
            float h1 = sigf(go1) * tanhap(cn1);
            *(float2*)(nxt + hstore) = make_float2(h0, h1);
        }

        // commit prefetched x(t+1)
        if (t + 1 < Tt) nxt[xk * XS + xr] = pf;

        __syncthreads();   // one barrier per step
    }

    // ---- Head: t=511 (odd) wrote nxt = xhA ----
    if (tid < ROWS) {
        float s = lin_b[0];
        #pragma unroll
        for (int m = 0; m < Hh; m++)
            s = fmaf(xhA[(INP + m) * XS + tid], lin_w[m], s);
        out[row0 + tid] = s;
    }
}

extern "C" void kernel_launch(void* const* d_in, const int* in_sizes, int n_in,
                              void* d_out, int out_size)
{
    const size_t smem_bytes =
        (size_t)(KTOT * Gg + 2 * KTOT * XS) * sizeof(float);   // 85120 B
    cudaFuncSetAttribute(bayes_lstm_kernel,
                         cudaFuncAttributeMaxDynamicSharedMemorySize,
                         (int)smem_bytes);
    bayes_lstm_kernel<<<GRID, NTH, smem_bytes>>>(
        (const float*)d_in[0],  (const float*)d_in[1],  (const float*)d_in[2],
        (const float*)d_in[3],  (const float*)d_in[4],  (const float*)d_in[5],
        (const float*)d_in[6],  (const float*)d_in[7],  (const float*)d_in[8],
        (const float*)d_in[9],  (const float*)d_in[10], (const float*)d_in[11],
        (float*)d_out);
}

// round 13
// speedup vs baseline: 1.5014x; 1.0425x over previous
#include <cuda_runtime.h>
#include <math.h>

#define Bsz  4096
#define Tt   512
#define INP  25
#define Hh   50
#define Gg   200
#define KTOT 76          // padded (row 75 = zero weights)
#define KSPL 38          // kh0: k in [0,38), kh1: [38,76)
#define ROWS 28
#define NTH  704         // 22 warps
#define GRID 147
#define XS2  56          // duplicated xh row stride: 28 rows x 2 copies

typedef unsigned long long u64;

__device__ __forceinline__ float tanhap(float v) {
    float r; asm("tanh.approx.f32 %0, %1;" : "=f"(r) : "f"(v)); return r;
}
__device__ __forceinline__ float sigf(float v) {
    return fmaf(0.5f, tanhap(0.5f * v), 0.5f);
}
__device__ __forceinline__ u64 pack2(float lo, float hi) {
    u64 d; asm("mov.b64 %0, {%1, %2};" : "=l"(d) : "f"(lo), "f"(hi)); return d;
}
__device__ __forceinline__ void unpack2(u64 d, float& lo, float& hi) {
    asm("mov.b64 {%0, %1}, %2;" : "=f"(lo), "=f"(hi) : "l"(d));
}
__device__ __forceinline__ u64 fma2(u64 a, u64 b, u64 c) {
    u64 d; asm("fma.rn.f32x2 %0, %1, %2, %3;" : "=l"(d) : "l"(a), "l"(b), "l"(c)); return d;
}
__device__ __forceinline__ u64 add2(u64 a, u64 b) {
    u64 d; asm("add.rn.f32x2 %0, %1, %2;" : "=l"(d) : "l"(a), "l"(b)); return d;
}
__device__ __forceinline__ u64 shfl_xor64(u64 v, int m) {
    float lo, hi; unpack2(v, lo, hi);
    lo = __shfl_xor_sync(0xffffffffu, lo, m);
    hi = __shfl_xor_sync(0xffffffffu, hi, m);
    return pack2(lo, hi);
}

__global__ void __launch_bounds__(NTH, 1)
bayes_lstm_kernel(const float* __restrict__ x,
                  const float* __restrict__ wi_mu, const float* __restrict__ wi_rho,
                  const float* __restrict__ wh_mu, const float* __restrict__ wh_rho,
                  const float* __restrict__ b_mu,  const float* __restrict__ b_rho,
                  const float* __restrict__ lin_w, const float* __restrict__ lin_b,
                  const float* __restrict__ eps_wi, const float* __restrict__ eps_wh,
                  const float* __restrict__ eps_b,
                  float* __restrict__ out)
{
    extern __shared__ float sm[];
    float* w_s = sm;                     // [76][Gg] gate-interleaved: w_s[k][jj*4+g] = W[k][g*50+jj]
    float* xhA = w_s + KTOT * Gg;        // [76][XS2] buf 0, DUPLICATED: [k][2r]=[k][2r+1]=val
    float* xhB = xhA + KTOT * XS2;       // [76][XS2] buf 1

    const int tid  = threadIdx.x;
    const long row0 = (long)blockIdx.x * ROWS;

    // ---- One-time: sample fused weights into gate-interleaved layout ----
    for (int i = tid; i < 75 * Gg; i += NTH) {
        int k = i / Gg, col = i - k * Gg;          // col = g*50 + jj
        float mu, rho, ep;
        if (k < INP) { mu = wi_mu[i]; rho = wi_rho[i]; ep = eps_wi[i]; }
        else { int i2 = i - INP * Gg; mu = wh_mu[i2]; rho = wh_rho[i2]; ep = eps_wh[i2]; }
        int g = col / Hh, jj = col - g * Hh;
        w_s[k * Gg + jj * 4 + g] = fmaf(log1pf(__expf(rho)), ep, mu);
    }
    // zero pad weight row 75; h rows of buf 0; row 75 of both xh buffers
    for (int i = tid; i < Gg; i += NTH) w_s[75 * Gg + i] = 0.0f;
    for (int i = tid; i < Hh * XS2; i += NTH) xhA[INP * XS2 + i] = 0.0f;
    for (int i = tid; i < XS2; i += NTH) { xhA[75 * XS2 + i] = 0.0f; xhB[75 * XS2 + i] = 0.0f; }
    // x(t=0) into buf 0 (700 elems, duplicated)
    {
        const int r = tid / INP, k = tid % INP;
        if (tid < INP * ROWS) {
            float v = 0.0f;
            if (row0 + r < Bsz) v = x[(size_t)(row0 + r) * (Tt * INP) + k];
            *(float2*)(xhA + k * XS2 + 2 * r) = make_float2(v, v);
        }
    }

    // ---- Task map: pair of lane-adjacent threads per (jj, 4-row) tile (R9 map) ----
    const bool act  = (tid < 700);
    const int  tile = act ? (tid >> 1) : 349;
    const int  kh   = tid & 1;
    const int  jj   = tile % 50;         // h-column
    const int  rr0  = (tile / 50) * 4;   // rows rr0..rr0+3
    const int  kbeg = kh ? KSPL : 0;

    // bias gate-pairs (kh==0 lanes only; flows through the bidirectional reduction)
    u64 biasIF = 0ull, biasGO = 0ull;
    if (kh == 0) {
        float bi = fmaf(log1pf(__expf(b_rho[jj])),           eps_b[jj],           b_mu[jj]);
        float bf = fmaf(log1pf(__expf(b_rho[Hh + jj])),      eps_b[Hh + jj],      b_mu[Hh + jj]);
        float bg = fmaf(log1pf(__expf(b_rho[2 * Hh + jj])),  eps_b[2 * Hh + jj],  b_mu[2 * Hh + jj]);
        float bo = fmaf(log1pf(__expf(b_rho[3 * Hh + jj])),  eps_b[3 * Hh + jj],  b_mu[3 * Hh + jj]);
        biasIF = pack2(bi, bf);
        biasGO = pack2(bg, bo);
    }

    // x prefetch map (1 elem/thread)
    const int  pr = tid / INP, pk = tid % INP;
    const bool pf_ok = (tid < INP * ROWS) && (row0 + pr < Bsz);
    const size_t pf_base = pf_ok ? ((size_t)(row0 + pr) * (Tt * INP) + pk) : 0;

    // cell state in registers: this lane owns rows rr0+2*kh, rr0+2*kh+1
    float c0 = 0.0f, c1 = 0.0f;

    const float* wp = w_s + jj * 4;
    const int hstore = (INP + jj) * XS2 + (rr0 + 2 * kh) * 2;   // 16B-aligned
    __syncthreads();

    for (int t = 0; t < Tt; ++t) {
        const float* cur = (t & 1) ? xhB : xhA;
        float*       nxt = (t & 1) ? xhA : xhB;

        float pf = 0.0f;
        if (pf_ok && t + 1 < Tt) pf = x[pf_base + (size_t)(t + 1) * INP];

        // ---- Gate GEMM: acc (gate-pair, row). All fma2 operands are natural
        //      float4 halves — no real pack instructions in the loop. ----
        u64 aIF0 = biasIF, aIF1 = biasIF, aIF2 = biasIF, aIF3 = biasIF;
        u64 aGO0 = biasGO, aGO1 = biasGO, aGO2 = biasGO, aGO3 = biasGO;

        const float* wk = wp + kbeg * Gg;
        const float* vk = cur + rr0 * 2 + kbeg * XS2;
        #pragma unroll 2
        for (int i = 0; i < KSPL; ++i) {
            float4 w4 = *(const float4*)(wk);      // (w_i, w_f, w_g, w_o) of column jj
            float4 hA = *(const float4*)(vk);      // (h0, h0, h1, h1)  duplicated
            float4 hB = *(const float4*)(vk + 4);  // (h2, h2, h3, h3)
            wk += Gg; vk += XS2;
            u64 wIF = pack2(w4.x, w4.y);           // adjacent regs: ~free
            u64 wGO = pack2(w4.z, w4.w);
            u64 h0 = pack2(hA.x, hA.y);            // adjacent regs: ~free
            u64 h1 = pack2(hA.z, hA.w);
            u64 h2 = pack2(hB.x, hB.y);
            u64 h3 = pack2(hB.z, hB.w);
            aIF0 = fma2(wIF, h0, aIF0);  aGO0 = fma2(wGO, h0, aGO0);
            aIF1 = fma2(wIF, h1, aIF1);  aGO1 = fma2(wGO, h1, aGO1);
            aIF2 = fma2(wIF, h2, aIF2);  aGO2 = fma2(wGO, h2, aGO2);
            aIF3 = fma2(wIF, h3, aIF3);  aGO3 = fma2(wGO, h3, aGO3);
        }

        // ---- Bidirectional pair reduction: both lanes get full sums ----
        aIF0 = add2(aIF0, shfl_xor64(aIF0, 1));
        aIF1 = add2(aIF1, shfl_xor64(aIF1, 1));
        aIF2 = add2(aIF2, shfl_xor64(aIF2, 1));
        aIF3 = add2(aIF3, shfl_xor64(aIF3, 1));
        aGO0 = add2(aGO0, shfl_xor64(aGO0, 1));
        aGO1 = add2(aGO1, shfl_xor64(aGO1, 1));
        aGO2 = add2(aGO2, shfl_xor64(aGO2, 1));
        aGO3 = add2(aGO3, shfl_xor64(aGO3, 1));

        // ---- In-register epilogue: this lane's 2 rows (rows rr0+2kh, rr0+2kh+1) ----
        {
            u64 uIF0 = kh ? aIF2 : aIF0;
            u64 uIF1 = kh ? aIF3 : aIF1;
            u64 uGO0 = kh ? aGO2 : aGO0;
            u64 uGO1 = kh ? aGO3 : aGO1;
            float gi0, gf0, gi1, gf1, gg0, go0, gg1, go1;
            unpack2(uIF0, gi0, gf0);
            unpack2(uIF1, gi1, gf1);
            unpack2(uGO0, gg0, go0);
            unpack2(uGO1, gg1, go1);
            float cn0 = fmaf(sigf(gf0), c0, sigf(gi0) * tanhap(gg0));
            float cn1 = fmaf(sigf(gf1), c1, sigf(gi1) * tanhap(gg1));
            c0 = cn0; c1 = cn1;
            float h0 = sigf(go0) * tanhap(cn0);
            float h1 = sigf(go1) * tanhap(cn1);
            if (act)
                *(float4*)(nxt + hstore) = make_float4(h0, h0, h1, h1);   // duplicated
        }

        // commit prefetched x(t+1), duplicated
        if (pf_ok && t + 1 < Tt)
            *(float2*)(nxt + pk * XS2 + 2 * pr) = make_float2(pf, pf);

        __syncthreads();   // one barrier per step
    }

    // ---- Head: t=511 (odd) wrote nxt = xhA ----
    if (tid < ROWS && row0 + tid < Bsz) {
        float s = lin_b[0];
        #pragma unroll
        for (int m = 0; m < Hh; m++)
            s = fmaf(xhA[(INP + m) * XS2 + 2 * tid], lin_w[m], s);
        out[row0 + tid] = s;
    }
}

extern "C" void kernel_launch(void* const* d_in, const int* in_sizes, int n_in,
                              void* d_out, int out_size)
{
    const size_t smem_bytes =
        (size_t)(KTOT * Gg + 2 * KTOT * XS2) * sizeof(float);   // 94848 B
    cudaFuncSetAttribute(bayes_lstm_kernel,
                         cudaFuncAttributeMaxDynamicSharedMemorySize,
                         (int)smem_bytes);
    bayes_lstm_kernel<<<GRID, NTH, smem_bytes>>>(
        (const float*)d_in[0],  (const float*)d_in[1],  (const float*)d_in[2],
        (const float*)d_in[3],  (const float*)d_in[4],  (const float*)d_in[5],
        (const float*)d_in[6],  (const float*)d_in[7],  (const float*)d_in[8],
        (const float*)d_in[9],  (const float*)d_in[10], (const float*)d_in[11],
        (float*)d_out);
}